// round 11
// baseline (speedup 1.0000x reference)
#include <cuda_runtime.h>
#include <cuda_bf16.h>
#include <cfloat>
#include <cstdint>

// ResidualVectorQuantizer, exact argmin via bf16-MMA prefilter + scalar verify.
// B=16,E=64,H=64,W=64 -> N=65536 tokens; K=1024, NC=8 stages.
//
// Exact reference numerics (validated rel_err==0 in rounds 1-6, 8, 10):
//   r2  = sequential sum of rounded squares of res (e ascending)
//   dot = sequential fused-FMA over e ascending
//   d   = fl(fl(r2 - fl(2*dot)) + cb2), argmin first-index tie-break
//   res -= q elementwise rounded; quant = ((q0+q1)+...)+q7
//
// R11: warp-autonomous design. Each warp owns 16 tokens end-to-end; full
// stage codebook (bf16-packed, 132KB) + exact cb2 (4KB) in smem. Only 2
// __syncthreads per stage (B-buffer reuse); all other work is warp-local.
// Scores never materialize: pass 1 = fp32 scores in regs -> per-token min;
// pass 2 = bitwise-identical recompute -> emit k with t <= min + MARGIN
// into warp-local candidates, then exact scalar verify (R6 numerics).
// MARGIN=2e-3 > bf16 worst-case score error (~1.05e-3, now WITHOUT the
// fp16-store term). CAP=256/warp = 16 cand/token headroom (R6 validated 12).

#define NTOK   65536
#define EDIM   64
#define KCB    1024
#define NCODE  8
#define MTOK   128         // tokens per CTA (16 per warp)
#define TPB    256
#define NWARP  8
#define BP     1032        // B smem pitch in words (1032%32==8: conflict-free)
#define RPITCH 68          // res row pitch (floats)
#define CAP    256         // candidates per warp (16 tokens)
#define MARGIN 2e-3f

// packed bf16 pairs along e: word(e2,k) = {lo=cb[k][2e2], hi=cb[k][2e2+1]}
__device__ unsigned g_cbt[NCODE * (EDIM/2) * KCB];
__device__ float    g_cb2[NCODE * KCB];         // exact ||cb||^2

__device__ __forceinline__ unsigned packbf(float lo, float hi) {
    unsigned r;
    asm("cvt.rn.bf16x2.f32 %0, %1, %2;" : "=r"(r) : "f"(hi), "f"(lo));
    return r;
}

__device__ __forceinline__ void mma_bf16(float& c0, float& c1, float& c2, float& c3,
                                         unsigned a0, unsigned a1, unsigned a2, unsigned a3,
                                         unsigned b0, unsigned b1) {
    asm volatile(
        "mma.sync.aligned.m16n8k16.row.col.f32.bf16.bf16.f32 "
        "{%0,%1,%2,%3}, {%4,%5,%6,%7}, {%8,%9}, {%0,%1,%2,%3};\n"
        : "+f"(c0), "+f"(c1), "+f"(c2), "+f"(c3)
        : "r"(a0), "r"(a1), "r"(a2), "r"(a3), "r"(b0), "r"(b1));
}

// ---- precompute: exact cb2 ----
__global__ void cb2_kernel(const float* __restrict__ cb)
{
    const int i = blockIdx.x * blockDim.x + threadIdx.x;   // 0..8191
    const float* row = cb + (size_t)i * EDIM;
    float c2 = 0.0f;
#pragma unroll
    for (int e = 0; e < EDIM; e++)
        c2 = __fadd_rn(c2, __fmul_rn(row[e], row[e]));
    g_cb2[i] = c2;
}

// ---- precompute: transpose + bf16-pack codebook to [s][e2][k] ----
__global__ void cbt_kernel(const float* __restrict__ cb)
{
    __shared__ float tile[32][33];       // [n_local][e_local]
    const int s  = blockIdx.z;
    const int n0 = blockIdx.x * 32;
    const int e0 = blockIdx.y * 32;
    const int tx = threadIdx.x, ty = threadIdx.y;
#pragma unroll
    for (int i = 0; i < 32; i += 8)
        tile[ty + i][tx] = cb[((size_t)s * KCB + (n0 + ty + i)) * EDIM + e0 + tx];
    __syncthreads();
#pragma unroll
    for (int i = 0; i < 2; i++) {
        int e2l = ty + i * 8;
        unsigned wv = packbf(tile[tx][2*e2l], tile[tx][2*e2l + 1]);
        g_cbt[((size_t)s * (EDIM/2) + (e0/2 + e2l)) * KCB + n0 + tx] = wv;
    }
}

struct Cand {
    int   cnt;
    int   pad[3];
    int   tok[CAP];           // local token row 0..15
    int   kk[CAP];            // k index 0..1023
    float dd[CAP];            // exact distance
};

// smem segment sizes (bytes)
#define BS_BYTES   (32 * BP * 4)               // 132096
#define C2S_BYTES  (KCB * 4)                   // 4096
#define RES_BYTES  (MTOK * RPITCH * 4)         // 34816
#define CAND_BYTES (NWARP * (int)sizeof(Cand)) // 8*3088 = 24704
#define R2S_BYTES  (MTOK * 4)                  // 512
#define SEL_BYTES  (MTOK * 4)                  // 512
#define HIST_BYTES (NCODE * MTOK * 4)          // 4096
#define SMEM_BYTES (BS_BYTES + C2S_BYTES + RES_BYTES + CAND_BYTES + \
                    R2S_BYTES + SEL_BYTES + HIST_BYTES)   // 200832

__global__ __launch_bounds__(TPB, 1)
void rvq_kernel(const float* __restrict__ emb,
                const float* __restrict__ cb,
                float* __restrict__ out)
{
    extern __shared__ char smem[];
    unsigned* bsw  = (unsigned*)smem;                       // [32][BP]
    float*    c2s  = (float*)(smem + BS_BYTES);             // [1024]
    float*    res  = (float*)(smem + BS_BYTES + C2S_BYTES); // [128][RPITCH]
    Cand*     cands= (Cand*)(smem + BS_BYTES + C2S_BYTES + RES_BYTES);
    float*    r2s  = (float*)((char*)cands + CAND_BYTES);
    int*      sel  = (int*)((char*)r2s + R2S_BYTES);
    int*      hist = (int*)((char*)sel + SEL_BYTES);        // [s][tok]

    const int tid  = threadIdx.x;
    const int w    = tid >> 5;      // 0..7
    const int lane = tid & 31;
    const int qr   = lane >> 2;     // 0..7
    const int qc   = lane & 3;      // 0..3

    // ---- init: load embeddings into res smem ----
    {
        const int tok = tid & 127;
        const int ec  = tid >> 7;       // 0..1
        const int n   = blockIdx.x * MTOK + tok;
        const int b   = n >> 12;
        const int hw  = n & 4095;
        const float* ep = emb + (size_t)b * (EDIM * 4096) + hw;
#pragma unroll
        for (int j = 0; j < 32; j++) {
            int e = ec * 32 + j;
            res[tok * RPITCH + e] = ep[(size_t)e * 4096];
        }
    }
    __syncthreads();

#pragma unroll 1
    for (int s = 0; s < NCODE; s++) {
        __syncthreads();    // all warps done reading previous stage's B
        // ---- load full stage codebook (packed bf16) + exact cb2 ----
        {
            const uint4* gsrc = (const uint4*)(g_cbt + (size_t)s * 32 * KCB);
#pragma unroll
            for (int j = 0; j < 32; j++) {
                int idx = j * TPB + tid;       // 0..8191
                int e2  = idx >> 8;            // 0..31
                int c4  = idx & 255;           // 0..255
                uint4 v = __ldg(gsrc + e2 * 256 + c4);
                *(uint4*)(bsw + e2 * BP + c4 * 4) = v;
            }
#pragma unroll
            for (int j = 0; j < 4; j++)
                c2s[j * TPB + tid] = __ldg(g_cb2 + s * KCB + j * TPB + tid);
        }
        __syncthreads();

        // ---- A fragments for this warp's 16 tokens (16 regs) ----
        const int r0 = w * 16 + qr;
        unsigned a[16];
        {
            const float* p0 = res + (size_t)r0 * RPITCH;
            const float* p1 = p0 + 8 * RPITCH;
#pragma unroll
            for (int ks = 0; ks < 4; ks++) {
                int c = 16 * ks + 2 * qc;
                a[ks*4+0] = packbf(p0[c],   p0[c+1]);
                a[ks*4+1] = packbf(p1[c],   p1[c+1]);
                a[ks*4+2] = packbf(p0[c+8], p0[c+9]);
                a[ks*4+3] = packbf(p1[c+8], p1[c+9]);
            }
        }
        // ---- exact r2 for this warp's 16 tokens ----
        if (lane < 16) {
            const float* rr = res + (size_t)(w * 16 + lane) * RPITCH;
            float r2 = 0.0f;
#pragma unroll
            for (int e = 0; e < EDIM; e++)
                r2 = __fadd_rn(r2, __fmul_rn(rr[e], rr[e]));
            r2s[w * 16 + lane] = r2;
        }
        __syncwarp();

        // ---- pass 1: full K scan, track per-row minima in registers ----
        float min0 = FLT_MAX, min1 = FLT_MAX;
#pragma unroll 2
        for (int kc = 0; kc < 64; kc++) {
            const int n0 = kc * 16;
            float c0=0.f,c1=0.f,c2=0.f,c3=0.f,c4v=0.f,c5=0.f,c6=0.f,c7=0.f;
            const unsigned* bp = bsw + n0 + qr;
#pragma unroll
            for (int ks = 0; ks < 4; ks++) {
                unsigned b00 = bp[(ks*8     + qc) * BP];
                unsigned b01 = bp[(ks*8 + 4 + qc) * BP];
                unsigned b10 = bp[(ks*8     + qc) * BP + 8];
                unsigned b11 = bp[(ks*8 + 4 + qc) * BP + 8];
                mma_bf16(c0, c1, c2, c3,
                         a[ks*4], a[ks*4+1], a[ks*4+2], a[ks*4+3], b00, b01);
                mma_bf16(c4v, c5, c6, c7,
                         a[ks*4], a[ks*4+1], a[ks*4+2], a[ks*4+3], b10, b11);
            }
            const int cc0 = n0 + 2*qc, cc1 = cc0 + 8;
            float2 z0 = *(const float2*)(c2s + cc0);
            float2 z1 = *(const float2*)(c2s + cc1);
            float t0 = fmaf(-2.f, c0,  z0.x), t1 = fmaf(-2.f, c1,  z0.y);
            float t2 = fmaf(-2.f, c2,  z0.x), t3 = fmaf(-2.f, c3,  z0.y);
            float t4 = fmaf(-2.f, c4v, z1.x), t5 = fmaf(-2.f, c5,  z1.y);
            float t6 = fmaf(-2.f, c6,  z1.x), t7 = fmaf(-2.f, c7,  z1.y);
            min0 = fminf(min0, fminf(fminf(t0, t1), fminf(t4, t5)));  // row qr
            min1 = fminf(min1, fminf(fminf(t2, t3), fminf(t6, t7)));  // row qr+8
        }
        // quad-reduce (lanes qr*4..qr*4+3 share a token row)
        min0 = fminf(min0, __shfl_xor_sync(0xffffffffu, min0, 1));
        min0 = fminf(min0, __shfl_xor_sync(0xffffffffu, min0, 2));
        min1 = fminf(min1, __shfl_xor_sync(0xffffffffu, min1, 1));
        min1 = fminf(min1, __shfl_xor_sync(0xffffffffu, min1, 2));
        const float thr0 = min0 + MARGIN;
        const float thr1 = min1 + MARGIN;

        Cand* cd = cands + w;
        if (lane == 0) cd->cnt = 0;
        __syncwarp();

        // ---- pass 2: bitwise-identical recompute, emit candidates ----
#pragma unroll 2
        for (int kc = 0; kc < 64; kc++) {
            const int n0 = kc * 16;
            float c0=0.f,c1=0.f,c2=0.f,c3=0.f,c4v=0.f,c5=0.f,c6=0.f,c7=0.f;
            const unsigned* bp = bsw + n0 + qr;
#pragma unroll
            for (int ks = 0; ks < 4; ks++) {
                unsigned b00 = bp[(ks*8     + qc) * BP];
                unsigned b01 = bp[(ks*8 + 4 + qc) * BP];
                unsigned b10 = bp[(ks*8     + qc) * BP + 8];
                unsigned b11 = bp[(ks*8 + 4 + qc) * BP + 8];
                mma_bf16(c0, c1, c2, c3,
                         a[ks*4], a[ks*4+1], a[ks*4+2], a[ks*4+3], b00, b01);
                mma_bf16(c4v, c5, c6, c7,
                         a[ks*4], a[ks*4+1], a[ks*4+2], a[ks*4+3], b10, b11);
            }
            const int cc0 = n0 + 2*qc, cc1 = cc0 + 8;
            float2 z0 = *(const float2*)(c2s + cc0);
            float2 z1 = *(const float2*)(c2s + cc1);
            float t0 = fmaf(-2.f, c0,  z0.x), t1 = fmaf(-2.f, c1,  z0.y);
            float t2 = fmaf(-2.f, c2,  z0.x), t3 = fmaf(-2.f, c3,  z0.y);
            float t4 = fmaf(-2.f, c4v, z1.x), t5 = fmaf(-2.f, c5,  z1.y);
            float t6 = fmaf(-2.f, c6,  z1.x), t7 = fmaf(-2.f, c7,  z1.y);
            if (t0 <= thr0) { int p = atomicAdd(&cd->cnt, 1);
                              if (p < CAP) { cd->tok[p] = qr;     cd->kk[p] = cc0;     } }
            if (t1 <= thr0) { int p = atomicAdd(&cd->cnt, 1);
                              if (p < CAP) { cd->tok[p] = qr;     cd->kk[p] = cc0 + 1; } }
            if (t4 <= thr0) { int p = atomicAdd(&cd->cnt, 1);
                              if (p < CAP) { cd->tok[p] = qr;     cd->kk[p] = cc1;     } }
            if (t5 <= thr0) { int p = atomicAdd(&cd->cnt, 1);
                              if (p < CAP) { cd->tok[p] = qr;     cd->kk[p] = cc1 + 1; } }
            if (t2 <= thr1) { int p = atomicAdd(&cd->cnt, 1);
                              if (p < CAP) { cd->tok[p] = qr + 8; cd->kk[p] = cc0;     } }
            if (t3 <= thr1) { int p = atomicAdd(&cd->cnt, 1);
                              if (p < CAP) { cd->tok[p] = qr + 8; cd->kk[p] = cc0 + 1; } }
            if (t6 <= thr1) { int p = atomicAdd(&cd->cnt, 1);
                              if (p < CAP) { cd->tok[p] = qr + 8; cd->kk[p] = cc1;     } }
            if (t7 <= thr1) { int p = atomicAdd(&cd->cnt, 1);
                              if (p < CAP) { cd->tok[p] = qr + 8; cd->kk[p] = cc1 + 1; } }
        }
        __syncwarp();
        const int ncand = min(cd->cnt, CAP);

        // ---- exact evaluation of all candidates (reference numerics) ----
        for (int base = 0; base < ncand; base += 32) {
            int i = base + lane;
            if (i < ncand) {
                int trow = cd->tok[i];
                int k    = cd->kk[i];
                int tok  = w * 16 + trow;
                const float4* q4 = (const float4*)(cb + ((size_t)(s * KCB + k)) * EDIM);
                const float* rr = res + (size_t)tok * RPITCH;
                float dot = 0.0f;
#pragma unroll
                for (int ii = 0; ii < 16; ii++) {
                    float4 q = __ldg(q4 + ii);
                    dot = __fmaf_rn(rr[4*ii+0], q.x, dot);
                    dot = __fmaf_rn(rr[4*ii+1], q.y, dot);
                    dot = __fmaf_rn(rr[4*ii+2], q.z, dot);
                    dot = __fmaf_rn(rr[4*ii+3], q.w, dot);
                }
                cd->dd[i] = __fadd_rn(__fsub_rn(r2s[tok], __fmul_rn(2.0f, dot)),
                                      c2s[k]);
            }
        }
        __syncwarp();
        // ---- per-token select with first-index tie-break ----
        if (lane < 16) {
            float bd = FLT_MAX; int bk = KCB;
            for (int i = 0; i < ncand; i++) {
                if (cd->tok[i] == lane) {
                    float d = cd->dd[i]; int k = cd->kk[i];
                    if (d < bd || (d == bd && k < bk)) { bd = d; bk = k; }
                }
            }
            sel[w * 16 + lane] = bk;
            hist[s * MTOK + w * 16 + lane] = bk;
        }
        __syncwarp();

        // ---- residual update (exact), warp-local ----
        {
            int tok  = w * 16 + (lane >> 1);   // 2 lanes per token
            int half = lane & 1;               // 32 floats each
            int k    = sel[tok];
            const float4* qp = (const float4*)(cb + ((size_t)(s * KCB + k)) * EDIM) + half * 8;
            float* rr = res + (size_t)tok * RPITCH + half * 32;
#pragma unroll
            for (int ii = 0; ii < 8; ii++) {
                float4 q  = __ldg(qp + ii);
                float4 rv = *(float4*)(rr + 4*ii);
                rv.x = __fsub_rn(rv.x, q.x);
                rv.y = __fsub_rn(rv.y, q.y);
                rv.z = __fsub_rn(rv.z, q.z);
                rv.w = __fsub_rn(rv.w, q.w);
                *(float4*)(rr + 4*ii) = rv;
            }
        }
        __syncwarp();
    }
    __syncthreads();   // hist complete (epilogue crosses warp boundaries)

    // ---- final epilogue: quant = ((q0+q1)+q2)...+q7, exact order ----
    {
        const int tok = tid & 127;
        const int ec  = tid >> 7;          // 0..1
        const int e0  = ec * 32;
        const int n   = blockIdx.x * MTOK + tok;
        const int b   = n >> 12;
        const int hw  = n & 4095;

        float4 acc[8];
        {
            int k = hist[0 * MTOK + tok];
            const float4* qp = (const float4*)(cb + ((size_t)(0 * KCB + k)) * EDIM + e0);
#pragma unroll
            for (int ii = 0; ii < 8; ii++) acc[ii] = __ldg(qp + ii);
        }
#pragma unroll
        for (int s = 1; s < NCODE; s++) {
            int k = hist[s * MTOK + tok];
            const float4* qp = (const float4*)(cb + ((size_t)(s * KCB + k)) * EDIM + e0);
#pragma unroll
            for (int ii = 0; ii < 8; ii++) {
                float4 q = __ldg(qp + ii);
                acc[ii].x = __fadd_rn(acc[ii].x, q.x);
                acc[ii].y = __fadd_rn(acc[ii].y, q.y);
                acc[ii].z = __fadd_rn(acc[ii].z, q.z);
                acc[ii].w = __fadd_rn(acc[ii].w, q.w);
            }
        }
        float* op = out + (size_t)b * (EDIM * 4096) + hw;
#pragma unroll
        for (int ii = 0; ii < 8; ii++) {
            op[(size_t)(e0 + 4*ii + 0) * 4096] = acc[ii].x;
            op[(size_t)(e0 + 4*ii + 1) * 4096] = acc[ii].y;
            op[(size_t)(e0 + 4*ii + 2) * 4096] = acc[ii].z;
            op[(size_t)(e0 + 4*ii + 3) * 4096] = acc[ii].w;
        }
    }
}

extern "C" void kernel_launch(void* const* d_in, const int* in_sizes, int n_in,
                              void* d_out, int out_size)
{
    const float* emb = (const float*)d_in[0];   // [16,64,64,64]
    const float* cb  = (const float*)d_in[1];   // [8,1024,64]
    float* out = (float*)d_out;
    (void)in_sizes; (void)n_in; (void)out_size;

    cudaFuncSetAttribute(rvq_kernel, cudaFuncAttributeMaxDynamicSharedMemorySize,
                         SMEM_BYTES);

    cbt_kernel<<<dim3(32, 2, 8), dim3(32, 8)>>>(cb);
    cb2_kernel<<<(NCODE * KCB) / 256, 256>>>(cb);
    rvq_kernel<<<NTOK / MTOK, TPB, SMEM_BYTES>>>(emb, cb, out);
}